// round 16
// baseline (speedup 1.0000x reference)
#include <cuda_runtime.h>
#include <cuda_bf16.h>
#include <cuda_fp16.h>
#include <stdint.h>

// ---------------------------------------------------------------------------
// LlamaAttention: S=2048, HID=4096, NH=32, NKV=8, D=128
// Projections: fp16 warp-MMA GEMM. Q/K: B hi+lo (2 MMAs). V/O: B single.
// Flash: all single fp16 operands (Q regs, K single dbuf, V single), 4 CTA/SM.
// RoPE fused in QKV epilogue. HMMA-only path.
// ---------------------------------------------------------------------------

#define S_LEN 2048
#define HID   4096
#define NH    32
#define NKV   8
#define HD    128
#define KVDIM (NKV * HD)   // 1024
#define KDIM  4096

// fp16 GEMM operands
__device__ __half g_h1[S_LEN * KDIM];
__device__ __half g_wq1[HID * KDIM],   g_wq2[HID * KDIM];
__device__ __half g_wk1[KVDIM * KDIM], g_wk2[KVDIM * KDIM];
__device__ __half g_wv1[KVDIM * KDIM];
__device__ __half g_wo1[HID * KDIM];
__device__ __half g_at1[S_LEN * KDIM];

// attention operands (all single fp16)
__device__ __half g_q1[S_LEN * HID];
__device__ __half g_k1[S_LEN * KVDIM];
__device__ __half g_v16[S_LEN * KVDIM];
__device__ __half g_vt1[KVDIM * S_LEN];

__device__ __forceinline__ uint32_t pack_hl_f16(float f0, float f1, uint32_t& lo) {
    __half2 h = __floats2half2_rn(f0, f1);
    float r0 = f0 - __half2float(h.x);
    float r1 = f1 - __half2float(h.y);
    __half2 l = __floats2half2_rn(r0, r1);
    lo = *(uint32_t*)&l;
    return *(uint32_t*)&h;
}

// ---------------------------------------------------------------------------
// fused split: hidden single; wq/wk pair; wv/wo single.
// ---------------------------------------------------------------------------
#define N_HID (S_LEN * KDIM)
#define N_WQ  (HID * KDIM)
#define N_WKV (KVDIM * KDIM)
#define SEG0  N_HID
#define SEG1  (SEG0 + N_WQ)
#define SEG2  (SEG1 + N_WKV)
#define SEG3  (SEG2 + N_WKV)
#define SEG4  (SEG3 + N_WQ)
#define SPLIT_GRID (SEG4 / (8 * 256))

__device__ __forceinline__ void split8_pair(const float* src, __half* h1,
                                            __half* h2, int off) {
    float4 f[2];
    f[0] = *(const float4*)(src + off);
    f[1] = *(const float4*)(src + off + 4);
    __half2 o1[4], o2[4];
#pragma unroll
    for (int j = 0; j < 2; j++) {
        const float v[4] = {f[j].x, f[j].y, f[j].z, f[j].w};
#pragma unroll
        for (int p = 0; p < 2; p++) {
            __half a = __float2half_rn(v[p * 2]);
            __half b = __float2half_rn(v[p * 2 + 1]);
            __half ra = __float2half_rn(v[p * 2] - __half2float(a));
            __half rb = __float2half_rn(v[p * 2 + 1] - __half2float(b));
            o1[j * 2 + p] = __halves2half2(a, b);
            o2[j * 2 + p] = __halves2half2(ra, rb);
        }
    }
    *(uint4*)(h1 + off) = *(uint4*)o1;
    *(uint4*)(h2 + off) = *(uint4*)o2;
}

__device__ __forceinline__ void split8_single(const float* src, __half* h1, int off) {
    float4 f[2];
    f[0] = *(const float4*)(src + off);
    f[1] = *(const float4*)(src + off + 4);
    __half2 o1[4];
    o1[0] = __floats2half2_rn(f[0].x, f[0].y);
    o1[1] = __floats2half2_rn(f[0].z, f[0].w);
    o1[2] = __floats2half2_rn(f[1].x, f[1].y);
    o1[3] = __floats2half2_rn(f[1].z, f[1].w);
    *(uint4*)(h1 + off) = *(uint4*)o1;
}

__global__ void split_all(const float* __restrict__ hidden,
                          const float* __restrict__ wq,
                          const float* __restrict__ wk,
                          const float* __restrict__ wv,
                          const float* __restrict__ wo) {
    int g = (blockIdx.x * blockDim.x + threadIdx.x) * 8;
    if (g < SEG0)      split8_single(hidden, g_h1, g);
    else if (g < SEG1) split8_pair(wq, g_wq1, g_wq2, g - SEG0);
    else if (g < SEG2) split8_pair(wk, g_wk1, g_wk2, g - SEG1);
    else if (g < SEG3) split8_single(wv, g_wv1, g - SEG2);
    else               split8_single(wo, g_wo1, g - SEG3);
}

// ---------------------------------------------------------------------------
// warp-MMA primitives
// ---------------------------------------------------------------------------
__device__ __forceinline__ void ldsm_x4(uint32_t addr, uint32_t& r0, uint32_t& r1,
                                        uint32_t& r2, uint32_t& r3) {
    asm volatile("ldmatrix.sync.aligned.m8n8.x4.shared.b16 {%0,%1,%2,%3}, [%4];"
                 : "=r"(r0), "=r"(r1), "=r"(r2), "=r"(r3) : "r"(addr));
}

__device__ __forceinline__ void mma_f16(float* c, const uint32_t* a, const uint32_t* b) {
    asm volatile(
        "mma.sync.aligned.m16n8k16.row.col.f32.f16.f16.f32 "
        "{%0,%1,%2,%3},{%4,%5,%6,%7},{%8,%9},{%0,%1,%2,%3};"
        : "+f"(c[0]), "+f"(c[1]), "+f"(c[2]), "+f"(c[3])
        : "r"(a[0]), "r"(a[1]), "r"(a[2]), "r"(a[3]), "r"(b[0]), "r"(b[1]));
}

// ---------------------------------------------------------------------------
// fp16 GEMM body: C = A1·B1 (+ A1·B2 if NB=2). Block 256x128, warp 64x64,
// BK=64, 256 threads, 3-stage cp.async, 144B-padded rows.
// MODE: 0 = fp32 out, 1 = RoPE + fp16 single, 3 = fp16 single (no RoPE).
// ---------------------------------------------------------------------------
#define GBK  64
#define LDT  144
#define A_T  (256 * LDT)
#define B_T  (128 * LDT)
#define STG  (A_T + 2 * B_T)
#define GEMM_SMEM (3 * STG)              // 221184

template <int NB, int MODE>
__device__ __forceinline__ void gemm_body_f16(
    const __half* __restrict__ A1,
    const __half* __restrict__ B1, const __half* __restrict__ B2,
    float* __restrict__ Cf, __half* __restrict__ Ch1,
    const float* __restrict__ cosb, const float* __restrict__ sinb,
    int N, int bm, int bn, char* smem) {
    const int tid = threadIdx.x;
    const int lane = tid & 31;
    const int warp = tid >> 5;
    const int wr = warp >> 1;
    const int wc = warp & 1;
    uint32_t sbase = (uint32_t)__cvta_generic_to_shared(smem);

    float acc[4][8][4];
#pragma unroll
    for (int mi = 0; mi < 4; mi++)
#pragma unroll
        for (int ni = 0; ni < 8; ni++)
#pragma unroll
            for (int t = 0; t < 4; t++) acc[mi][ni][t] = 0.f;

    auto load_stage = [&](int s, int it) {
        const int kbase = it * GBK;
        uint32_t dst0 = sbase + s * STG;
        const int NCH = (NB == 2) ? 16 : 12;
#pragma unroll
        for (int i = 0; i < NCH; i++) {
            int c = tid + i * 256;
            const __half* gsrc;
            uint32_t daddr;
            if (c < 2048) {
                int row = c >> 3;
                int ch = c & 7;
                gsrc = A1 + (size_t)(bm + row) * KDIM + kbase + ch * 8;
                daddr = dst0 + row * LDT + ch * 16;
            } else {
                int cb = c - 2048;
                int mat = cb >> 10;
                int idx = cb & 1023;
                int row = idx >> 3;
                int ch = idx & 7;
                gsrc = (mat ? B2 : B1) + (size_t)(bn + row) * KDIM + kbase + ch * 8;
                daddr = dst0 + A_T + mat * B_T + row * LDT + ch * 16;
            }
            asm volatile("cp.async.cg.shared.global [%0], [%1], 16;"
                         :: "r"(daddr), "l"(gsrc));
        }
        asm volatile("cp.async.commit_group;");
    };

    const int NIT = KDIM / GBK;
    load_stage(0, 0);
    load_stage(1, 1);

    const int brow = (lane & 7) + ((lane >> 4) << 3);
    const int bch = (lane >> 3) & 1;

    for (int it = 0; it < NIT; it++) {
        asm volatile("cp.async.wait_group 1;");
        __syncthreads();
        if (it + 2 < NIT) load_stage((it + 2) % 3, it + 2);
        else              asm volatile("cp.async.commit_group;");

        uint32_t sa = sbase + (it % 3) * STG;
#pragma unroll
        for (int ks = 0; ks < 4; ks++) {
            uint32_t af[4][4];
#pragma unroll
            for (int mi = 0; mi < 4; mi++) {
                uint32_t off = (uint32_t)((wr * 64 + mi * 16 + (lane & 15)) * LDT +
                                          ks * 32 + ((lane >> 4) & 1) * 16);
                ldsm_x4(sa + off, af[mi][0], af[mi][1], af[mi][2], af[mi][3]);
            }
#pragma unroll
            for (int half = 0; half < 2; half++) {
                uint32_t b1[4][2], b2[4][2];
#pragma unroll
                for (int np = 0; np < 2; np++) {
                    uint32_t off = (uint32_t)((wc * 64 + half * 32 + np * 16 + brow) * LDT +
                                              ks * 32 + bch * 16);
                    uint32_t r0, r1, r2, r3;
                    ldsm_x4(sa + A_T + off, r0, r1, r2, r3);
                    b1[np * 2][0] = r0; b1[np * 2][1] = r1;
                    b1[np * 2 + 1][0] = r2; b1[np * 2 + 1][1] = r3;
                    if (NB == 2) {
                        ldsm_x4(sa + A_T + B_T + off, r0, r1, r2, r3);
                        b2[np * 2][0] = r0; b2[np * 2][1] = r1;
                        b2[np * 2 + 1][0] = r2; b2[np * 2 + 1][1] = r3;
                    }
                }
#pragma unroll
                for (int mi = 0; mi < 4; mi++)
#pragma unroll
                    for (int nf = 0; nf < 4; nf++) {
                        float* a = acc[mi][half * 4 + nf];
                        mma_f16(a, af[mi], b1[nf]);
                        if (NB == 2) mma_f16(a, af[mi], b2[nf]);
                    }
            }
        }
    }

    if (MODE == 0) {
#pragma unroll
        for (int mi = 0; mi < 4; mi++) {
            const int r0 = bm + wr * 64 + mi * 16 + (lane >> 2);
#pragma unroll
            for (int ni = 0; ni < 8; ni++) {
                const int col = bn + wc * 64 + ni * 8 + (lane & 3) * 2;
                *(float2*)&Cf[(size_t)r0 * N + col] = make_float2(acc[mi][ni][0], acc[mi][ni][1]);
                *(float2*)&Cf[(size_t)(r0 + 8) * N + col] = make_float2(acc[mi][ni][2], acc[mi][ni][3]);
            }
        }
    } else if (MODE == 3) {
#pragma unroll
        for (int mi = 0; mi < 4; mi++) {
            const int r0 = bm + wr * 64 + mi * 16 + (lane >> 2);
#pragma unroll
            for (int ni = 0; ni < 8; ni++) {
                const int col = bn + wc * 64 + ni * 8 + (lane & 3) * 2;
                __half2 p0 = __floats2half2_rn(acc[mi][ni][0], acc[mi][ni][1]);
                __half2 p1 = __floats2half2_rn(acc[mi][ni][2], acc[mi][ni][3]);
                *(uint32_t*)&Ch1[(size_t)r0 * N + col] = *(uint32_t*)&p0;
                *(uint32_t*)&Ch1[(size_t)(r0 + 8) * N + col] = *(uint32_t*)&p1;
            }
        }
    } else {
        // RoPE + fp16 single store
#pragma unroll
        for (int mi = 0; mi < 4; mi++) {
            const int r0 = bm + wr * 64 + mi * 16 + (lane >> 2);
            const int r1 = r0 + 8;
#pragma unroll
            for (int ni = 0; ni < 8; ni++) {
                const int col = bn + wc * 64 + ni * 8 + (lane & 3) * 2;
                const int i = (col & 127) >> 1;
                float c0 = cosb[r0 * 64 + i], s0 = sinb[r0 * 64 + i];
                float c1 = cosb[r1 * 64 + i], s1 = sinb[r1 * 64 + i];
                float a0 = acc[mi][ni][0], b0 = acc[mi][ni][1];
                float a1 = acc[mi][ni][2], b1 = acc[mi][ni][3];
                float x0 = a0 * c0 - b0 * s0, y0 = a0 * s0 + b0 * c0;
                float x1 = a1 * c1 - b1 * s1, y1 = a1 * s1 + b1 * c1;
                __half2 p0 = __floats2half2_rn(x0, y0);
                __half2 p1 = __floats2half2_rn(x1, y1);
                *(uint32_t*)&Ch1[(size_t)r0 * N + col] = *(uint32_t*)&p0;
                *(uint32_t*)&Ch1[(size_t)r1 * N + col] = *(uint32_t*)&p1;
            }
        }
    }
}

__global__ __launch_bounds__(256, 1) void gemm_qkv(const float* __restrict__ cosb,
                                                   const float* __restrict__ sinb) {
    extern __shared__ char smem[];
    const int y = blockIdx.y;
    const int bm = blockIdx.x * 256;
    if (y < 32) {
        gemm_body_f16<2, 1>(g_h1, g_wq1, g_wq2, nullptr, g_q1,
                            cosb, sinb, HID, bm, y * 128, smem);
    } else if (y < 40) {
        gemm_body_f16<2, 1>(g_h1, g_wk1, g_wk2, nullptr, g_k1,
                            cosb, sinb, KVDIM, bm, (y - 32) * 128, smem);
    } else {
        gemm_body_f16<1, 3>(g_h1, g_wv1, nullptr, nullptr, g_v16,
                            nullptr, nullptr, KVDIM, bm, (y - 40) * 128, smem);
    }
}

__global__ __launch_bounds__(256, 1) void gemm_o(float* __restrict__ out) {
    extern __shared__ char smem[];
    gemm_body_f16<1, 0>(g_at1, g_wo1, nullptr, out, nullptr,
                        nullptr, nullptr, HID, blockIdx.x * 256, blockIdx.y * 128, smem);
}

// ---------------------------------------------------------------------------
// transpose: v16[S,1024] fp16 -> vt1[1024, S] fp16
// ---------------------------------------------------------------------------
__global__ void transpose_v(const __half* __restrict__ v,
                            __half* __restrict__ th) {
    __shared__ __half tile[32][34];
    const int bs = blockIdx.x * 32;
    const int bd = blockIdx.y * 32;
    const int tx = threadIdx.x;
    const int ty = threadIdx.y;
#pragma unroll
    for (int i = 0; i < 4; i++) {
        int sy = ty * 4 + i;
        tile[sy][tx] = v[(size_t)(bs + sy) * KVDIM + bd + tx];
    }
    __syncthreads();
#pragma unroll
    for (int i = 0; i < 4; i++) {
        int dy = ty * 4 + i;
        th[(size_t)(bd + dy) * S_LEN + bs + tx] = tile[tx][dy];
    }
}

// ---------------------------------------------------------------------------
// Flash attention: all single fp16 (Q regs, K single dbuf, V single).
// BQ=64, 128 thr, 53KB SMEM -> 4 CTA/SM. exp2 softmax. fp16 attn out.
// Grid (32 qb reversed, 32 h).
// ---------------------------------------------------------------------------
#define QLDT 272
#define VLDT 144
#define FK0  0
#define FK1  17408
#define FV   34816
#define FLASH_SMEM (FV + 18432)   // 53248

__global__ __launch_bounds__(128, 4) void flash_tc(
    const __half* __restrict__ q1, const __half* __restrict__ k1,
    const __half* __restrict__ vt1,
    __half* __restrict__ o1) {
    extern __shared__ char sm[];
    const int qb = (int)gridDim.x - 1 - (int)blockIdx.x;
    const int h  = blockIdx.y;
    const int kvh = h >> 2;
    const int tid = threadIdx.x;
    const int lane = tid & 31;
    const int w = tid >> 5;
    const int q0 = qb * 64;
    const float scale2 = 0.12751744685137577f;   // (1/sqrt(128)) * log2(e)
    uint32_t sb = (uint32_t)__cvta_generic_to_shared(sm);

    const int brow = (lane & 7) + ((lane >> 4) << 3);
    const int bch = (lane >> 3) & 1;

    // stage Q (single) into FK1, then load fragments into registers
    for (int i = tid; i < 1024; i += 128) {
        int r = i >> 4;
        int c = i & 15;
        const __half* src = q1 + (size_t)(q0 + r) * HID + h * HD + c * 8;
        *(uint4*)(sm + FK1 + r * QLDT + c * 16) = *(const uint4*)src;
    }
    __syncthreads();
    uint32_t qf[8][4];
#pragma unroll
    for (int kf = 0; kf < 8; kf++) {
        uint32_t aoff = (uint32_t)((w * 16 + (lane & 15)) * QLDT + kf * 32 + (lane >> 4) * 16);
        ldsm_x4(sb + FK1 + aoff, qf[kf][0], qf[kf][1], qf[kf][2], qf[kf][3]);
    }
    __syncthreads();

    auto loadK = [&](int kb) {
        const int k0 = kb * 64;
        uint32_t kdst = sb + ((kb & 1) ? FK1 : FK0);
#pragma unroll
        for (int i0 = 0; i0 < 8; i0++) {
            int i = tid + i0 * 128;
            int r = i >> 4;
            int c = i & 15;
            const void* src = k1 + (size_t)(k0 + r) * KVDIM + kvh * HD + c * 8;
            asm volatile("cp.async.cg.shared.global [%0], [%1], 16;"
                         :: "r"(kdst + r * QLDT + c * 16), "l"(src));
        }
        asm volatile("cp.async.commit_group;");
    };
    auto loadV = [&](int kb) {
        const int k0 = kb * 64;
        uint32_t vdst = sb + FV;
#pragma unroll
        for (int i0 = 0; i0 < 8; i0++) {
            int i = tid + i0 * 128;
            int r = i >> 3;
            int c = i & 7;
            const void* src = vt1 + (size_t)(kvh * HD + r) * S_LEN + k0 + c * 8;
            asm volatile("cp.async.cg.shared.global [%0], [%1], 16;"
                         :: "r"(vdst + r * VLDT + c * 16), "l"(src));
        }
        asm volatile("cp.async.commit_group;");
    };

    float m0 = -1e30f, m1 = -1e30f, l0 = 0.f, l1 = 0.f;
    float oa[16][4];
#pragma unroll
    for (int i = 0; i < 16; i++)
#pragma unroll
        for (int t = 0; t < 4; t++) oa[i][t] = 0.f;

    const int r0g = q0 + w * 16 + (lane >> 2);
    const int r1g = r0g + 8;

    loadK(0);

    for (int kb = 0; kb <= qb; kb++) {
        const int k0 = kb * 64;
        loadV(kb);
        if (kb < qb) loadK(kb + 1);
        else         asm volatile("cp.async.commit_group;");
        asm volatile("cp.async.wait_group 2;");   // K(kb) complete
        __syncthreads();

        const uint32_t kbase = sb + ((kb & 1) ? FK1 : FK0);

        // S = Q K^T (single x single: 2 MMAs per np)
        float s[8][4];
#pragma unroll
        for (int nf = 0; nf < 8; nf++)
#pragma unroll
            for (int t = 0; t < 4; t++) s[nf][t] = 0.f;

#pragma unroll
        for (int kf = 0; kf < 8; kf++) {
#pragma unroll
            for (int np = 0; np < 4; np++) {
                uint32_t boff = (uint32_t)((np * 16 + brow) * QLDT + kf * 32 + bch * 16);
                uint32_t b1[4];
                ldsm_x4(kbase + boff, b1[0], b1[1], b1[2], b1[3]);
                mma_f16(s[np * 2], qf[kf], b1);
                mma_f16(s[np * 2 + 1], qf[kf], b1 + 2);
            }
        }

#pragma unroll
        for (int nf = 0; nf < 8; nf++)
#pragma unroll
            for (int t = 0; t < 4; t++) s[nf][t] *= scale2;
        if (kb == qb) {
#pragma unroll
            for (int nf = 0; nf < 8; nf++) {
                int cg = k0 + nf * 8 + (lane & 3) * 2;
                if (cg > r0g)     s[nf][0] = -1e30f;
                if (cg + 1 > r0g) s[nf][1] = -1e30f;
                if (cg > r1g)     s[nf][2] = -1e30f;
                if (cg + 1 > r1g) s[nf][3] = -1e30f;
            }
        }

        float mx0 = -1e30f, mx1 = -1e30f;
#pragma unroll
        for (int nf = 0; nf < 8; nf++) {
            mx0 = fmaxf(mx0, fmaxf(s[nf][0], s[nf][1]));
            mx1 = fmaxf(mx1, fmaxf(s[nf][2], s[nf][3]));
        }
        mx0 = fmaxf(mx0, __shfl_xor_sync(0xffffffffu, mx0, 1));
        mx0 = fmaxf(mx0, __shfl_xor_sync(0xffffffffu, mx0, 2));
        mx1 = fmaxf(mx1, __shfl_xor_sync(0xffffffffu, mx1, 1));
        mx1 = fmaxf(mx1, __shfl_xor_sync(0xffffffffu, mx1, 2));
        float mn0 = fmaxf(m0, mx0);
        float mn1 = fmaxf(m1, mx1);
        float c0 = exp2f(m0 - mn0);
        float c1 = exp2f(m1 - mn1);
        m0 = mn0; m1 = mn1;
        float rs0 = 0.f, rs1 = 0.f;
#pragma unroll
        for (int nf = 0; nf < 8; nf++) {
            s[nf][0] = exp2f(s[nf][0] - m0); rs0 += s[nf][0];
            s[nf][1] = exp2f(s[nf][1] - m0); rs0 += s[nf][1];
            s[nf][2] = exp2f(s[nf][2] - m1); rs1 += s[nf][2];
            s[nf][3] = exp2f(s[nf][3] - m1); rs1 += s[nf][3];
        }
        rs0 += __shfl_xor_sync(0xffffffffu, rs0, 1);
        rs0 += __shfl_xor_sync(0xffffffffu, rs0, 2);
        rs1 += __shfl_xor_sync(0xffffffffu, rs1, 1);
        rs1 += __shfl_xor_sync(0xffffffffu, rs1, 2);
        l0 = l0 * c0 + rs0;
        l1 = l1 * c1 + rs1;
#pragma unroll
        for (int i = 0; i < 16; i++) {
            oa[i][0] *= c0; oa[i][1] *= c0;
            oa[i][2] *= c1; oa[i][3] *= c1;
        }

        asm volatile("cp.async.wait_group 1;");   // V(kb) complete
        __syncthreads();

        // O += P V (single x single: 2 MMAs per np)
#pragma unroll
        for (int kf2 = 0; kf2 < 4; kf2++) {
            uint32_t pah[4];
            {
                __half2 t0 = __floats2half2_rn(s[2 * kf2][0], s[2 * kf2][1]);
                __half2 t1 = __floats2half2_rn(s[2 * kf2][2], s[2 * kf2][3]);
                __half2 t2 = __floats2half2_rn(s[2 * kf2 + 1][0], s[2 * kf2 + 1][1]);
                __half2 t3 = __floats2half2_rn(s[2 * kf2 + 1][2], s[2 * kf2 + 1][3]);
                pah[0] = *(uint32_t*)&t0;
                pah[1] = *(uint32_t*)&t1;
                pah[2] = *(uint32_t*)&t2;
                pah[3] = *(uint32_t*)&t3;
            }
#pragma unroll
            for (int np = 0; np < 8; np++) {
                uint32_t voff = (uint32_t)((np * 16 + brow) * VLDT + kf2 * 32 + bch * 16);
                uint32_t v1[4];
                ldsm_x4(sb + FV + voff, v1[0], v1[1], v1[2], v1[3]);
                mma_f16(oa[np * 2], pah, v1);
                mma_f16(oa[np * 2 + 1], pah, v1 + 2);
            }
        }
        __syncthreads();
    }

    const float inv0 = 1.0f / l0;
    const float inv1 = 1.0f / l1;
#pragma unroll
    for (int nf2 = 0; nf2 < 16; nf2++) {
        int col = h * HD + nf2 * 8 + (lane & 3) * 2;
        __half2 p0 = __floats2half2_rn(oa[nf2][0] * inv0, oa[nf2][1] * inv0);
        __half2 p1 = __floats2half2_rn(oa[nf2][2] * inv1, oa[nf2][3] * inv1);
        *(uint32_t*)&o1[(size_t)r0g * HID + col] = *(uint32_t*)&p0;
        *(uint32_t*)&o1[(size_t)r1g * HID + col] = *(uint32_t*)&p1;
    }
}

// ---------------------------------------------------------------------------
// launcher
// ---------------------------------------------------------------------------
extern "C" void kernel_launch(void* const* d_in, const int* in_sizes, int n_in,
                              void* d_out, int out_size) {
    const float* hidden = (const float*)d_in[0];
    const float* cosb = (const float*)d_in[2];
    const float* sinb = (const float*)d_in[3];
    const float* wq = (const float*)d_in[4];
    const float* wk = (const float*)d_in[5];
    const float* wv = (const float*)d_in[6];
    const float* wo = (const float*)d_in[7];
    float* out = (float*)d_out;

    __half *at1, *vt1, *q1, *k1, *v16;
    cudaGetSymbolAddress((void**)&at1, g_at1);
    cudaGetSymbolAddress((void**)&vt1, g_vt1);
    cudaGetSymbolAddress((void**)&q1, g_q1);
    cudaGetSymbolAddress((void**)&k1, g_k1);
    cudaGetSymbolAddress((void**)&v16, g_v16);

    split_all<<<SPLIT_GRID, 256>>>(hidden, wq, wk, wv, wo);

    cudaFuncSetAttribute(gemm_qkv, cudaFuncAttributeMaxDynamicSharedMemorySize,
                         GEMM_SMEM);
    cudaFuncSetAttribute(gemm_o, cudaFuncAttributeMaxDynamicSharedMemorySize,
                         GEMM_SMEM);

    gemm_qkv<<<dim3(S_LEN / 256, 48), 256, GEMM_SMEM>>>(cosb, sinb);

    transpose_v<<<dim3(S_LEN / 32, KVDIM / 32), dim3(32, 8)>>>(v16, vt1);

    cudaFuncSetAttribute(flash_tc, cudaFuncAttributeMaxDynamicSharedMemorySize,
                         FLASH_SMEM);
    flash_tc<<<dim3(32, 32), 128, FLASH_SMEM>>>(q1, k1, vt1, at1);

    gemm_o<<<dim3(S_LEN / 256, HID / 128), 256, GEMM_SMEM>>>(out);
}